// round 5
// baseline (speedup 1.0000x reference)
#include <cuda_runtime.h>
#include <cstdint>

typedef unsigned long long ull;

#define BB 2
#define NN 768
#define CS 768
#define HH 16
#define HD 48
#define CZ 128

// ----- scratch (static device globals: no allocation allowed) -----
__device__ float g_q [BB*NN*CS];
__device__ float g_k [BB*NN*CS];
__device__ float g_v [BB*NN*CS];
__device__ float g_g [BB*NN*CS];
__device__ float g_og[BB*NN*CS];
__device__ float g_bias  [(size_t)BB*HH*NN*NN];
__device__ float g_scores[(size_t)BB*HH*NN*NN];

// ----- packed f32x2 helpers -----
__device__ __forceinline__ ull pack2(float x, float y) {
    ull r; asm("mov.b64 %0, {%1, %2};" : "=l"(r) : "f"(x), "f"(y)); return r;
}
__device__ __forceinline__ ull dup2(float x) { return pack2(x, x); }
__device__ __forceinline__ void fma2(ull& d, ull a, ull b) {
    asm("fma.rn.f32x2 %0, %1, %2, %0;" : "+l"(d) : "l"(a), "l"(b));
}
__device__ __forceinline__ void unpack2(ull v, float& x, float& y) {
    asm("mov.b64 {%0, %1}, %2;" : "=f"(x), "=f"(y) : "l"(v));
}

// ----- tiled GEMM: C[m][n] = sum_k A[m][k]*W[n][k] (+bias, opt sigmoid) -----
// 128x128 block tile, BK=16, 256 threads, 8x8 per thread.
__device__ __forceinline__ void gemm_block(
    const float* __restrict__ A, const float* __restrict__ W,
    const float* __restrict__ bvec, float* __restrict__ C, int act,
    int m0, int n0)
{
    __shared__ __align__(16) float As[16][128];
    __shared__ __align__(16) float Ws[16][128];
    const int tid = threadIdx.x;
    const int lr = tid >> 1;              // row 0..127
    const int lq = (tid & 1) * 8;         // k sub-offset 0 or 8
    const int tx = tid & 15, ty = tid >> 4;

    ull acc[8][4];
#pragma unroll
    for (int i = 0; i < 8; i++)
#pragma unroll
        for (int j = 0; j < 4; j++) acc[i][j] = 0ULL;

    for (int kt = 0; kt < CS / 16; kt++) {
        const float* ap = A + (size_t)(m0 + lr) * CS + kt * 16 + lq;
        const float* wp = W + (size_t)(n0 + lr) * CS + kt * 16 + lq;
        float4 a0 = *(const float4*)ap;
        float4 a1 = *(const float4*)(ap + 4);
        float4 w0 = *(const float4*)wp;
        float4 w1 = *(const float4*)(wp + 4);
        As[lq+0][lr]=a0.x; As[lq+1][lr]=a0.y; As[lq+2][lr]=a0.z; As[lq+3][lr]=a0.w;
        As[lq+4][lr]=a1.x; As[lq+5][lr]=a1.y; As[lq+6][lr]=a1.z; As[lq+7][lr]=a1.w;
        Ws[lq+0][lr]=w0.x; Ws[lq+1][lr]=w0.y; Ws[lq+2][lr]=w0.z; Ws[lq+3][lr]=w0.w;
        Ws[lq+4][lr]=w1.x; Ws[lq+5][lr]=w1.y; Ws[lq+6][lr]=w1.z; Ws[lq+7][lr]=w1.w;
        __syncthreads();

#pragma unroll
        for (int k = 0; k < 16; k++) {
            float4 fa0 = *(const float4*)&As[k][ty*8];
            float4 fa1 = *(const float4*)&As[k][ty*8+4];
            ulonglong2 b01 = *(const ulonglong2*)&Ws[k][tx*8];
            ulonglong2 b23 = *(const ulonglong2*)&Ws[k][tx*8+4];
            float av[8] = {fa0.x,fa0.y,fa0.z,fa0.w,fa1.x,fa1.y,fa1.z,fa1.w};
#pragma unroll
            for (int i = 0; i < 8; i++) {
                ull ad = dup2(av[i]);
                fma2(acc[i][0], ad, b01.x);
                fma2(acc[i][1], ad, b01.y);
                fma2(acc[i][2], ad, b23.x);
                fma2(acc[i][3], ad, b23.y);
            }
        }
        __syncthreads();
    }

    float bv[8];
    if (bvec) {
        float4 b0 = *(const float4*)&bvec[n0 + tx*8];
        float4 b1 = *(const float4*)&bvec[n0 + tx*8 + 4];
        bv[0]=b0.x; bv[1]=b0.y; bv[2]=b0.z; bv[3]=b0.w;
        bv[4]=b1.x; bv[5]=b1.y; bv[6]=b1.z; bv[7]=b1.w;
    } else {
#pragma unroll
        for (int c = 0; c < 8; c++) bv[c] = 0.f;
    }

#pragma unroll
    for (int i = 0; i < 8; i++) {
        float r[8];
#pragma unroll
        for (int j = 0; j < 4; j++) unpack2(acc[i][j], r[2*j], r[2*j+1]);
#pragma unroll
        for (int c = 0; c < 8; c++) {
            r[c] += bv[c];
            if (act) r[c] = 1.f / (1.f + __expf(-r[c]));
        }
        float* cp = C + (size_t)(m0 + ty*8 + i) * CS + n0 + tx*8;
        *(float4*)cp     = make_float4(r[0], r[1], r[2], r[3]);
        *(float4*)(cp+4) = make_float4(r[4], r[5], r[6], r[7]);
    }
}

// K1: q/k/v/g projections
__global__ void __launch_bounds__(256) qkvg_kernel(
    const float* __restrict__ s,  const float* __restrict__ kin,
    const float* __restrict__ Wq, const float* __restrict__ bq,
    const float* __restrict__ Wk, const float* __restrict__ Wv,
    const float* __restrict__ Wg)
{
    const float* A; const float* W; const float* bv = nullptr;
    float* C; int act = 0;
    switch (blockIdx.z) {
        case 0:  A = s;   W = Wq; bv = bq; C = g_q; break;
        case 1:  A = kin; W = Wk;          C = g_k; break;
        case 2:  A = kin; W = Wv;          C = g_v; break;
        default: A = s;   W = Wg;          C = g_g; act = 1; break;
    }
    gemm_block(A, W, bv, C, act, blockIdx.y * 128, blockIdx.x * 128);
}

// K6: out = og @ Wo^T
__global__ void __launch_bounds__(256) outproj_kernel(
    const float* __restrict__ Wo, float* __restrict__ out)
{
    gemm_block(g_og, Wo, nullptr, out, 0, blockIdx.y * 128, blockIdx.x * 128);
}

// K2: bias[b,h,i,j] = LayerNorm(z[b,i,j,:]) . Wz[h,:]
__global__ void __launch_bounds__(256) biasproj_kernel(
    const float* __restrict__ z,   const float* __restrict__ lng,
    const float* __restrict__ lnb, const float* __restrict__ Wz)
{
    __shared__ __align__(16) ull A2[128][8];  // {g_c*Wz[2h], g_c*Wz[2h+1]}
    __shared__ float Sf[16], Cf[16];
    const int tid = threadIdx.x;
    if (tid < 128) {
        float gc = lng[tid];
#pragma unroll
        for (int h2 = 0; h2 < 8; h2++)
            A2[tid][h2] = pack2(gc * Wz[(2*h2)*CZ + tid], gc * Wz[(2*h2+1)*CZ + tid]);
    } else if (tid < 144) {
        int hh = tid - 128;
        float S = 0.f, Cc = 0.f;
        for (int c = 0; c < CZ; c++) {
            float w = Wz[hh*CZ + c];
            S  = fmaf(lng[c], w, S);
            Cc = fmaf(lnb[c], w, Cc);
        }
        Sf[hh] = S; Cf[hh] = Cc;
    }
    __syncthreads();

    const int idx = blockIdx.x * 256 + tid;  // (b,i,j) linear
    const int j = idx % NN;
    const int t = idx / NN;
    const int i = t % NN;
    const int b = t / NN;

    const float* zp = z + (size_t)idx * CZ;
    ull acc[8];
#pragma unroll
    for (int h2 = 0; h2 < 8; h2++) acc[h2] = 0ULL;
    float sum = 0.f, sumsq = 0.f;

#pragma unroll 4
    for (int c4 = 0; c4 < CZ/4; c4++) {
        float4 zv = *(const float4*)(zp + c4*4);
        float zz[4] = {zv.x, zv.y, zv.z, zv.w};
#pragma unroll
        for (int u = 0; u < 4; u++) {
            const int c = c4*4 + u;
            float zc = zz[u];
            sum += zc;
            sumsq = fmaf(zc, zc, sumsq);
            ull zd = dup2(zc);
            const ulonglong2* ap = (const ulonglong2*)&A2[c][0];
            ulonglong2 a01 = ap[0], a23 = ap[1], a45 = ap[2], a67 = ap[3];
            fma2(acc[0], zd, a01.x); fma2(acc[1], zd, a01.y);
            fma2(acc[2], zd, a23.x); fma2(acc[3], zd, a23.y);
            fma2(acc[4], zd, a45.x); fma2(acc[5], zd, a45.y);
            fma2(acc[6], zd, a67.x); fma2(acc[7], zd, a67.y);
        }
    }

    const float inv = 1.f / CZ;
    float mu   = sum * inv;
    float var  = sumsq * inv - mu*mu;
    float rstd = rsqrtf(var + 1e-5f);

    const size_t base = ((size_t)b*HH*NN + i) * NN + j;
    const size_t hs   = (size_t)NN * NN;
#pragma unroll
    for (int h2 = 0; h2 < 8; h2++) {
        float d0, d1; unpack2(acc[h2], d0, d1);
        g_bias[base + (size_t)(2*h2)  *hs] = rstd*(d0 - mu*Sf[2*h2])   + Cf[2*h2];
        g_bias[base + (size_t)(2*h2+1)*hs] = rstd*(d1 - mu*Sf[2*h2+1]) + Cf[2*h2+1];
    }
}

// K3: scores = q.k/sqrt(hd) + bias + (1-mask)*(-1e6)
__global__ void __launch_bounds__(256) scores_kernel(const float* __restrict__ mask)
{
    __shared__ __align__(16) float qt[HD][128];
    __shared__ __align__(16) float kt[HD][128];
    const int tid = threadIdx.x;
    const int h  = blockIdx.z & (HH-1);
    const int b  = blockIdx.z >> 4;
    const int i0 = blockIdx.y * 128;
    const int j0 = blockIdx.x * 128;

    for (int idx = tid; idx < 128 * (HD/4); idx += 256) {
        const int r  = idx / (HD/4);
        const int dq = idx % (HD/4);
        float4 v = *(const float4*)&g_q[((size_t)(b*NN + i0 + r))*CS + h*HD + dq*4];
        qt[dq*4+0][r]=v.x; qt[dq*4+1][r]=v.y; qt[dq*4+2][r]=v.z; qt[dq*4+3][r]=v.w;
        float4 w = *(const float4*)&g_k[((size_t)(b*NN + j0 + r))*CS + h*HD + dq*4];
        kt[dq*4+0][r]=w.x; kt[dq*4+1][r]=w.y; kt[dq*4+2][r]=w.z; kt[dq*4+3][r]=w.w;
    }
    __syncthreads();

    const int tx = tid & 15, ty = tid >> 4;
    ull acc[8][4];
#pragma unroll
    for (int i = 0; i < 8; i++)
#pragma unroll
        for (int j = 0; j < 4; j++) acc[i][j] = 0ULL;

#pragma unroll 8
    for (int d = 0; d < HD; d++) {
        float4 fa0 = *(const float4*)&qt[d][ty*8];
        float4 fa1 = *(const float4*)&qt[d][ty*8+4];
        ulonglong2 b01 = *(const ulonglong2*)&kt[d][tx*8];
        ulonglong2 b23 = *(const ulonglong2*)&kt[d][tx*8+4];
        float av[8] = {fa0.x,fa0.y,fa0.z,fa0.w,fa1.x,fa1.y,fa1.z,fa1.w};
#pragma unroll
        for (int i = 0; i < 8; i++) {
            ull ad = dup2(av[i]);
            fma2(acc[i][0], ad, b01.x);
            fma2(acc[i][1], ad, b01.y);
            fma2(acc[i][2], ad, b23.x);
            fma2(acc[i][3], ad, b23.y);
        }
    }

    const float scale = 0.14433756729740643f;  // 1/sqrt(48)
    float4 mk0 = *(const float4*)&mask[b*NN + j0 + tx*8];
    float4 mk1 = *(const float4*)&mask[b*NN + j0 + tx*8 + 4];
    float madd[8] = {(1.f-mk0.x)*(-1e6f),(1.f-mk0.y)*(-1e6f),
                     (1.f-mk0.z)*(-1e6f),(1.f-mk0.w)*(-1e6f),
                     (1.f-mk1.x)*(-1e6f),(1.f-mk1.y)*(-1e6f),
                     (1.f-mk1.z)*(-1e6f),(1.f-mk1.w)*(-1e6f)};

    const size_t bh = ((size_t)b*HH + h) * NN * NN;
#pragma unroll
    for (int i = 0; i < 8; i++) {
        const size_t roff = bh + (size_t)(i0 + ty*8 + i) * NN + j0 + tx*8;
        float r[8];
#pragma unroll
        for (int j = 0; j < 4; j++) unpack2(acc[i][j], r[2*j], r[2*j+1]);
        float4 bb0 = *(const float4*)&g_bias[roff];
        float4 bb1 = *(const float4*)&g_bias[roff + 4];
        float bsv[8] = {bb0.x,bb0.y,bb0.z,bb0.w,bb1.x,bb1.y,bb1.z,bb1.w};
#pragma unroll
        for (int c = 0; c < 8; c++) r[c] = fmaf(r[c], scale, bsv[c] + madd[c]);
        *(float4*)&g_scores[roff]     = make_float4(r[0], r[1], r[2], r[3]);
        *(float4*)&g_scores[roff + 4] = make_float4(r[4], r[5], r[6], r[7]);
    }
}

// K4: softmax over last dim, in-place on g_scores. One block per row.
__global__ void __launch_bounds__(256) softmax_kernel()
{
    __shared__ float red[256];
    const int tid = threadIdx.x;
    float* p = g_scores + (size_t)blockIdx.x * NN;

    float v0 = p[tid], v1 = p[tid + 256], v2 = p[tid + 512];
    float m = fmaxf(v0, fmaxf(v1, v2));
    red[tid] = m; __syncthreads();
    for (int s = 128; s > 0; s >>= 1) {
        if (tid < s) red[tid] = fmaxf(red[tid], red[tid + s]);
        __syncthreads();
    }
    m = red[0]; __syncthreads();

    v0 = __expf(v0 - m); v1 = __expf(v1 - m); v2 = __expf(v2 - m);
    red[tid] = v0 + v1 + v2; __syncthreads();
    for (int s = 128; s > 0; s >>= 1) {
        if (tid < s) red[tid] += red[tid + s];
        __syncthreads();
    }
    float inv = 1.f / red[0];
    p[tid] = v0 * inv; p[tid + 256] = v1 * inv; p[tid + 512] = v2 * inv;
}

// K5: og[b,i,h*48+d] = (sum_k attn[b,h,i,k]*v[b,k,h*48+d]) * g[b,i,h*48+d]
// Block: 64 rows x 48 cols for one (b,h); k tiles of 64.
__global__ void __launch_bounds__(256) ov_kernel()
{
    __shared__ __align__(16) float at[64][65];
    __shared__ __align__(16) float vt[64][48];
    const int tid = threadIdx.x;
    const int h  = blockIdx.y & (HH-1);
    const int b  = blockIdx.y >> 4;
    const int i0 = blockIdx.x * 64;
    const int tx = tid & 3;     // col group: 12 cols
    const int ty = tid >> 2;    // row 0..63

    const size_t bh = ((size_t)b*HH + h) * NN * NN;
    ull acc[6];
#pragma unroll
    for (int j = 0; j < 6; j++) acc[j] = 0ULL;

    for (int kt = 0; kt < NN / 64; kt++) {
        const int k0 = kt * 64;
        // load attn tile 64x64 (4 float4 per thread)
#pragma unroll
        for (int u = 0; u < 4; u++) {
            const int idx = tid + u * 256;          // 0..1023 float4 slots
            const int r = idx >> 4, q = idx & 15;
            float4 a = *(const float4*)&g_scores[bh + (size_t)(i0 + r)*NN + k0 + q*4];
            at[r][q*4+0]=a.x; at[r][q*4+1]=a.y; at[r][q*4+2]=a.z; at[r][q*4+3]=a.w;
        }
        // load v tile 64x48 (3 float4 per thread)
#pragma unroll
        for (int u = 0; u < 3; u++) {
            const int idx = tid + u * 256;          // 0..767 float4 slots
            const int r = idx / 12, q = idx % 12;
            *(float4*)&vt[r][q*4] =
                *(const float4*)&g_v[((size_t)(b*NN + k0 + r))*CS + h*HD + q*4];
        }
        __syncthreads();

#pragma unroll 8
        for (int k = 0; k < 64; k++) {
            ull ad = dup2(at[ty][k]);
            const ulonglong2* bp = (const ulonglong2*)&vt[k][tx*12];
            ulonglong2 b0 = bp[0], b1 = bp[1], b2 = bp[2];
            fma2(acc[0], ad, b0.x); fma2(acc[1], ad, b0.y);
            fma2(acc[2], ad, b1.x); fma2(acc[3], ad, b1.y);
            fma2(acc[4], ad, b2.x); fma2(acc[5], ad, b2.y);
        }
        __syncthreads();
    }

    const size_t off = ((size_t)(b*NN + i0 + ty))*CS + h*HD + tx*12;
    float r[12];
#pragma unroll
    for (int j = 0; j < 6; j++) unpack2(acc[j], r[2*j], r[2*j+1]);
    float4 g0 = *(const float4*)&g_g[off];
    float4 g1 = *(const float4*)&g_g[off + 4];
    float4 g2 = *(const float4*)&g_g[off + 8];
    float gv[12] = {g0.x,g0.y,g0.z,g0.w,g1.x,g1.y,g1.z,g1.w,g2.x,g2.y,g2.z,g2.w};
#pragma unroll
    for (int c = 0; c < 12; c++) r[c] *= gv[c];
    *(float4*)&g_og[off]     = make_float4(r[0], r[1], r[2],  r[3]);
    *(float4*)&g_og[off + 4] = make_float4(r[4], r[5], r[6],  r[7]);
    *(float4*)&g_og[off + 8] = make_float4(r[8], r[9], r[10], r[11]);
}

extern "C" void kernel_launch(void* const* d_in, const int* in_sizes, int n_in,
                              void* d_out, int out_size)
{
    const float* s    = (const float*)d_in[0];
    const float* z    = (const float*)d_in[1];
    const float* mask = (const float*)d_in[2];
    const float* kin  = (const float*)d_in[3];
    const float* Wq   = (const float*)d_in[4];
    const float* bq   = (const float*)d_in[5];
    const float* Wk   = (const float*)d_in[6];
    const float* Wv   = (const float*)d_in[7];
    const float* Wg   = (const float*)d_in[8];
    const float* lng  = (const float*)d_in[9];
    const float* lnb  = (const float*)d_in[10];
    const float* Wz   = (const float*)d_in[11];
    const float* Wo   = (const float*)d_in[12];
    float* out = (float*)d_out;

    qkvg_kernel<<<dim3(CS/128, BB*NN/128, 4), 256>>>(s, kin, Wq, bq, Wk, Wv, Wg);
    biasproj_kernel<<<BB*NN*NN/256, 256>>>(z, lng, lnb, Wz);
    scores_kernel<<<dim3(NN/128, NN/128, BB*HH), 256>>>(mask);
    softmax_kernel<<<BB*HH*NN, 256>>>();
    ov_kernel<<<dim3(NN/64, BB*HH), 256>>>();
    outproj_kernel<<<dim3(CS/128, BB*NN/128), 256>>>(Wo, out);
}

// round 7
// speedup vs baseline: 1.1743x; 1.1743x over previous
#include <cuda_runtime.h>
#include <cstdint>

typedef unsigned long long ull;

#define BB 2
#define NN 768
#define CS 768
#define HH 16
#define HD 48
#define CZ 128

#define IT 64      // attention i-tile rows
#define JT 64      // attention j-tile cols
#define PSS 68     // P tile row stride (pad for banks, keeps 8B align)

// ----- scratch (static device globals: no allocation allowed) -----
__device__ float g_q [BB*NN*CS];
__device__ float g_k [BB*NN*CS];
__device__ float g_v [BB*NN*CS];
__device__ float g_g [BB*NN*CS];
__device__ float g_og[BB*NN*CS];
__device__ float g_bias[(size_t)BB*HH*NN*NN];

// ----- packed f32x2 helpers -----
__device__ __forceinline__ ull pack2(float x, float y) {
    ull r; asm("mov.b64 %0, {%1, %2};" : "=l"(r) : "f"(x), "f"(y)); return r;
}
__device__ __forceinline__ ull dup2(float x) { return pack2(x, x); }
__device__ __forceinline__ void fma2(ull& d, ull a, ull b) {
    asm("fma.rn.f32x2 %0, %1, %2, %0;" : "+l"(d) : "l"(a), "l"(b));
}
__device__ __forceinline__ void mul2(ull& d, ull a) {
    asm("mul.rn.f32x2 %0, %0, %1;" : "+l"(d) : "l"(a));
}
__device__ __forceinline__ void unpack2(ull v, float& x, float& y) {
    asm("mov.b64 {%0, %1}, %2;" : "=f"(x), "=f"(y) : "l"(v));
}

// ----- tiled GEMM with register prefetch: C = A @ W^T (+bias, opt sigmoid) --
// 128x128 tile, BK=16, 256 threads, 8x8 per thread.
__device__ __forceinline__ void gemm_block(
    const float* __restrict__ A, const float* __restrict__ W,
    const float* __restrict__ bvec, float* __restrict__ C, int act,
    int m0, int n0)
{
    __shared__ __align__(16) float As[16][128];
    __shared__ __align__(16) float Ws[16][128];
    const int tid = threadIdx.x;
    const int lr = tid >> 1;
    const int lq = (tid & 1) * 8;
    const int tx = tid & 15, ty = tid >> 4;

    const float* ap = A + (size_t)(m0 + lr) * CS + lq;
    const float* wp = W + (size_t)(n0 + lr) * CS + lq;

    ull acc[8][4];
#pragma unroll
    for (int i = 0; i < 8; i++)
#pragma unroll
        for (int j = 0; j < 4; j++) acc[i][j] = 0ULL;

    float4 a0 = *(const float4*)ap;
    float4 a1 = *(const float4*)(ap + 4);
    float4 w0 = *(const float4*)wp;
    float4 w1 = *(const float4*)(wp + 4);

    for (int kt = 0; kt < CS / 16; kt++) {
        As[lq+0][lr]=a0.x; As[lq+1][lr]=a0.y; As[lq+2][lr]=a0.z; As[lq+3][lr]=a0.w;
        As[lq+4][lr]=a1.x; As[lq+5][lr]=a1.y; As[lq+6][lr]=a1.z; As[lq+7][lr]=a1.w;
        Ws[lq+0][lr]=w0.x; Ws[lq+1][lr]=w0.y; Ws[lq+2][lr]=w0.z; Ws[lq+3][lr]=w0.w;
        Ws[lq+4][lr]=w1.x; Ws[lq+5][lr]=w1.y; Ws[lq+6][lr]=w1.z; Ws[lq+7][lr]=w1.w;
        __syncthreads();

        if (kt + 1 < CS / 16) {                 // prefetch next k-tile
            const int ko = (kt + 1) * 16;
            a0 = *(const float4*)(ap + ko);
            a1 = *(const float4*)(ap + ko + 4);
            w0 = *(const float4*)(wp + ko);
            w1 = *(const float4*)(wp + ko + 4);
        }

#pragma unroll
        for (int k = 0; k < 16; k++) {
            float4 fa0 = *(const float4*)&As[k][ty*8];
            float4 fa1 = *(const float4*)&As[k][ty*8+4];
            ulonglong2 b01 = *(const ulonglong2*)&Ws[k][tx*8];
            ulonglong2 b23 = *(const ulonglong2*)&Ws[k][tx*8+4];
            float av[8] = {fa0.x,fa0.y,fa0.z,fa0.w,fa1.x,fa1.y,fa1.z,fa1.w};
#pragma unroll
            for (int i = 0; i < 8; i++) {
                ull ad = dup2(av[i]);
                fma2(acc[i][0], ad, b01.x);
                fma2(acc[i][1], ad, b01.y);
                fma2(acc[i][2], ad, b23.x);
                fma2(acc[i][3], ad, b23.y);
            }
        }
        __syncthreads();
    }

    float bv[8];
    if (bvec) {
        float4 b0 = *(const float4*)&bvec[n0 + tx*8];
        float4 b1 = *(const float4*)&bvec[n0 + tx*8 + 4];
        bv[0]=b0.x; bv[1]=b0.y; bv[2]=b0.z; bv[3]=b0.w;
        bv[4]=b1.x; bv[5]=b1.y; bv[6]=b1.z; bv[7]=b1.w;
    } else {
#pragma unroll
        for (int c = 0; c < 8; c++) bv[c] = 0.f;
    }

#pragma unroll
    for (int i = 0; i < 8; i++) {
        float r[8];
#pragma unroll
        for (int j = 0; j < 4; j++) unpack2(acc[i][j], r[2*j], r[2*j+1]);
#pragma unroll
        for (int c = 0; c < 8; c++) {
            r[c] += bv[c];
            if (act) r[c] = 1.f / (1.f + __expf(-r[c]));
        }
        float* cp = C + (size_t)(m0 + ty*8 + i) * CS + n0 + tx*8;
        *(float4*)cp     = make_float4(r[0], r[1], r[2], r[3]);
        *(float4*)(cp+4) = make_float4(r[4], r[5], r[6], r[7]);
    }
}

// K1: q/k/v/g projections
__global__ void __launch_bounds__(256) qkvg_kernel(
    const float* __restrict__ s,  const float* __restrict__ kin,
    const float* __restrict__ Wq, const float* __restrict__ bq,
    const float* __restrict__ Wk, const float* __restrict__ Wv,
    const float* __restrict__ Wg)
{
    const float* A; const float* W; const float* bv = nullptr;
    float* C; int act = 0;
    switch (blockIdx.z) {
        case 0:  A = s;   W = Wq; bv = bq; C = g_q; break;
        case 1:  A = kin; W = Wk;          C = g_k; break;
        case 2:  A = kin; W = Wv;          C = g_v; break;
        default: A = s;   W = Wg;          C = g_g; act = 1; break;
    }
    gemm_block(A, W, bv, C, act, blockIdx.y * 128, blockIdx.x * 128);
}

// K4: out = og @ Wo^T
__global__ void __launch_bounds__(256) outproj_kernel(
    const float* __restrict__ Wo, float* __restrict__ out)
{
    gemm_block(g_og, Wo, nullptr, out, 0, blockIdx.y * 128, blockIdx.x * 128);
}

// K2: bias[b,h,i,j] = LayerNorm(z[b,i,j,:]) . Wz[h,:]
__global__ void __launch_bounds__(256) biasproj_kernel(
    const float* __restrict__ z,   const float* __restrict__ lng,
    const float* __restrict__ lnb, const float* __restrict__ Wz)
{
    __shared__ __align__(16) ull A2[128][8];   // {g_c*Wz[2h], g_c*Wz[2h+1]}
    __shared__ float Sf[16], Cf[16];
    const int tid = threadIdx.x;
    if (tid < 128) {
        float gc = lng[tid];
#pragma unroll
        for (int h2 = 0; h2 < 8; h2++)
            A2[tid][h2] = pack2(gc * Wz[(2*h2)*CZ + tid], gc * Wz[(2*h2+1)*CZ + tid]);
    } else if (tid < 144) {
        int hh = tid - 128;
        float S = 0.f, Cc = 0.f;
        for (int c = 0; c < CZ; c++) {
            float w = Wz[hh*CZ + c];
            S  = fmaf(lng[c], w, S);
            Cc = fmaf(lnb[c], w, Cc);
        }
        Sf[hh] = S; Cf[hh] = Cc;
    }
    __syncthreads();

    const int idx = blockIdx.x * 256 + tid;
    const int j = idx % NN;
    const int t = idx / NN;
    const int i = t % NN;
    const int b = t / NN;

    const float* zp = z + (size_t)idx * CZ;
    ull acc[8];
#pragma unroll
    for (int h2 = 0; h2 < 8; h2++) acc[h2] = 0ULL;
    float sum = 0.f, sumsq = 0.f;

#pragma unroll 4
    for (int c4 = 0; c4 < CZ/4; c4++) {
        float4 zv = *(const float4*)(zp + c4*4);
        float zz[4] = {zv.x, zv.y, zv.z, zv.w};
#pragma unroll
        for (int u = 0; u < 4; u++) {
            const int c = c4*4 + u;
            float zc = zz[u];
            sum += zc;
            sumsq = fmaf(zc, zc, sumsq);
            ull zd = dup2(zc);
            const ulonglong2* ap = (const ulonglong2*)&A2[c][0];
            ulonglong2 a01 = ap[0], a23 = ap[1], a45 = ap[2], a67 = ap[3];
            fma2(acc[0], zd, a01.x); fma2(acc[1], zd, a01.y);
            fma2(acc[2], zd, a23.x); fma2(acc[3], zd, a23.y);
            fma2(acc[4], zd, a45.x); fma2(acc[5], zd, a45.y);
            fma2(acc[6], zd, a67.x); fma2(acc[7], zd, a67.y);
        }
    }

    const float inv = 1.f / CZ;
    float mu   = sum * inv;
    float var  = sumsq * inv - mu*mu;
    float rstd = rsqrtf(var + 1e-5f);

    const size_t base = ((size_t)b*HH*NN + i) * NN + j;
    const size_t hs   = (size_t)NN * NN;
#pragma unroll
    for (int h2 = 0; h2 < 8; h2++) {
        float d0, d1; unpack2(acc[h2], d0, d1);
        g_bias[base + (size_t)(2*h2)  *hs] = rstd*(d0 - mu*Sf[2*h2])   + Cf[2*h2];
        g_bias[base + (size_t)(2*h2+1)*hs] = rstd*(d1 - mu*Sf[2*h2+1]) + Cf[2*h2+1];
    }
}

__device__ __forceinline__ float shfl_max16(float v) {
    v = fmaxf(v, __shfl_xor_sync(0xffffffffu, v, 8));
    v = fmaxf(v, __shfl_xor_sync(0xffffffffu, v, 4));
    v = fmaxf(v, __shfl_xor_sync(0xffffffffu, v, 2));
    v = fmaxf(v, __shfl_xor_sync(0xffffffffu, v, 1));
    return v;
}
__device__ __forceinline__ float shfl_sum16(float v) {
    v += __shfl_xor_sync(0xffffffffu, v, 8);
    v += __shfl_xor_sync(0xffffffffu, v, 4);
    v += __shfl_xor_sync(0xffffffffu, v, 2);
    v += __shfl_xor_sync(0xffffffffu, v, 1);
    return v;
}

// K3: flash attention with pair bias + mask + gating (scores never hit HBM).
// Block = one (b,h,i-tile of 64 rows). Streams 64-wide j tiles; online softmax.
__global__ void __launch_bounds__(256) attn_kernel(const float* __restrict__ mask)
{
    extern __shared__ float sm[];
    float* qs = sm;                       // [48][64]  qs[d*IT + i]
    float* ks = sm + 48*IT;               // [48][64]  ks[d*JT + j]
    float* vs = ks + 48*JT;               // [64][48]  vs[j*48 + d]
    float* ps = vs + JT*48;               // [64][PSS]
    float* scale_s = ps + IT*PSS;         // [64]
    float* l_s = scale_s + IT;            // [64]

    const int tid = threadIdx.x;
    const int h  = blockIdx.y & (HH-1);
    const int b  = blockIdx.y >> 4;
    const int i0 = blockIdx.x * IT;
    const int tx = tid & 15, ty = tid >> 4;   // S layout: 4 rows x 4 cols
    const int tx2 = tid & 7, ty2 = tid >> 3;  // PV layout: 2 rows x 6 cols

    // load q tile transposed (once)
    for (int idx = tid; idx < IT * (HD/4); idx += 256) {
        const int r = idx / (HD/4), dq = idx % (HD/4);
        float4 v = *(const float4*)&g_q[((size_t)(b*NN + i0 + r))*CS + h*HD + dq*4];
        qs[(dq*4+0)*IT + r] = v.x; qs[(dq*4+1)*IT + r] = v.y;
        qs[(dq*4+2)*IT + r] = v.z; qs[(dq*4+3)*IT + r] = v.w;
    }

    float mrow[4] = {-1e30f, -1e30f, -1e30f, -1e30f};
    float lrow[4] = {0.f, 0.f, 0.f, 0.f};
    ull oacc[2][3];
#pragma unroll
    for (int r = 0; r < 2; r++)
#pragma unroll
        for (int c = 0; c < 3; c++) oacc[r][c] = 0ULL;

    const size_t bh = ((size_t)b*HH + h) * (size_t)NN * NN;
    const float scale = 0.14433756729740643f;   // 1/sqrt(48)

    for (int jt = 0; jt < NN / JT; jt++) {
        const int j0 = jt * JT;
        __syncthreads();   // prev PV done with ps/vs

        // load k tile (transposed) + v tile
        for (int idx = tid; idx < JT * (HD/4); idx += 256) {
            const int j = idx / (HD/4), dq = idx % (HD/4);
            const size_t go = ((size_t)(b*NN + j0 + j))*CS + h*HD + dq*4;
            float4 kv = *(const float4*)&g_k[go];
            ks[(dq*4+0)*JT + j] = kv.x; ks[(dq*4+1)*JT + j] = kv.y;
            ks[(dq*4+2)*JT + j] = kv.z; ks[(dq*4+3)*JT + j] = kv.w;
            float4 vv = *(const float4*)&g_v[go];
            *(float4*)&vs[j*48 + dq*4] = vv;
        }
        __syncthreads();

        // ---- S phase: 4 rows x 4 cols per thread ----
        ull acc[4][2];
#pragma unroll
        for (int i = 0; i < 4; i++) { acc[i][0] = 0ULL; acc[i][1] = 0ULL; }

#pragma unroll 4
        for (int d = 0; d < HD; d++) {
            float4 a = *(const float4*)&qs[d*IT + ty*4];
            ulonglong2 kb = *(const ulonglong2*)&ks[d*JT + tx*4];
            float av[4] = {a.x, a.y, a.z, a.w};
#pragma unroll
            for (int i = 0; i < 4; i++) {
                ull ad = dup2(av[i]);
                fma2(acc[i][0], ad, kb.x);
                fma2(acc[i][1], ad, kb.y);
            }
        }

        float4 mk = *(const float4*)&mask[b*NN + j0 + tx*4];
        float madd[4] = {(1.f-mk.x)*(-1e6f), (1.f-mk.y)*(-1e6f),
                         (1.f-mk.z)*(-1e6f), (1.f-mk.w)*(-1e6f)};

#pragma unroll
        for (int i = 0; i < 4; i++) {
            const int row = ty*4 + i;
            float sv[4];
            unpack2(acc[i][0], sv[0], sv[1]);
            unpack2(acc[i][1], sv[2], sv[3]);
            float4 bb = *(const float4*)&g_bias[bh + (size_t)(i0+row)*NN + j0 + tx*4];
            sv[0] = fmaf(sv[0], scale, bb.x + madd[0]);
            sv[1] = fmaf(sv[1], scale, bb.y + madd[1]);
            sv[2] = fmaf(sv[2], scale, bb.z + madd[2]);
            sv[3] = fmaf(sv[3], scale, bb.w + madd[3]);

            float rm = fmaxf(fmaxf(sv[0], sv[1]), fmaxf(sv[2], sv[3]));
            rm = shfl_max16(rm);
            float mn = fmaxf(mrow[i], rm);
            float p0 = __expf(sv[0] - mn), p1 = __expf(sv[1] - mn);
            float p2 = __expf(sv[2] - mn), p3 = __expf(sv[3] - mn);
            float rs = shfl_sum16(p0 + p1 + p2 + p3);
            float sc = __expf(mrow[i] - mn);
            lrow[i] = lrow[i] * sc + rs;
            mrow[i] = mn;
            *(float4*)&ps[row*PSS + tx*4] = make_float4(p0, p1, p2, p3);
            if (tx == 0) scale_s[row] = sc;
        }
        __syncthreads();

        // ---- PV phase: 2 rows x 6 cols per thread ----
        {
            const int r0 = ty2*2, r1 = ty2*2 + 1;
            ull d0 = dup2(scale_s[r0]);
            ull d1 = dup2(scale_s[r1]);
#pragma unroll
            for (int c = 0; c < 3; c++) { mul2(oacc[0][c], d0); mul2(oacc[1][c], d1); }

            const float* vbase = vs + tx2*6;
#pragma unroll 4
            for (int k = 0; k < JT; k += 2) {
                ull pk0 = *(const ull*)&ps[r0*PSS + k];
                ull pk1 = *(const ull*)&ps[r1*PSS + k];
                float p00, p01, p10, p11;
                unpack2(pk0, p00, p01);
                unpack2(pk1, p10, p11);
                const float* v0 = vbase + k*48;
                const float* v1 = v0 + 48;
                ull va0 = *(const ull*)(v0);
                ull va1 = *(const ull*)(v0 + 2);
                ull va2 = *(const ull*)(v0 + 4);
                ull vb0 = *(const ull*)(v1);
                ull vb1 = *(const ull*)(v1 + 2);
                ull vb2 = *(const ull*)(v1 + 4);
                ull a00 = dup2(p00), a10 = dup2(p10);
                fma2(oacc[0][0], a00, va0); fma2(oacc[0][1], a00, va1); fma2(oacc[0][2], a00, va2);
                fma2(oacc[1][0], a10, va0); fma2(oacc[1][1], a10, va1); fma2(oacc[1][2], a10, va2);
                ull a01 = dup2(p01), a11 = dup2(p11);
                fma2(oacc[0][0], a01, vb0); fma2(oacc[0][1], a01, vb1); fma2(oacc[0][2], a01, vb2);
                fma2(oacc[1][0], a11, vb0); fma2(oacc[1][1], a11, vb1); fma2(oacc[1][2], a11, vb2);
            }
        }
    }

    // publish l for PV-layout threads
    if (tx == 0) {
#pragma unroll
        for (int i = 0; i < 4; i++) l_s[ty*4 + i] = lrow[i];
    }
    __syncthreads();

    // epilogue: divide by l, gate, store
#pragma unroll
    for (int r = 0; r < 2; r++) {
        const int row = ty2*2 + r;
        const float inv = 1.f / l_s[row];
        const size_t off = ((size_t)(b*NN + i0 + row))*CS + h*HD + tx2*6;
#pragma unroll
        for (int c = 0; c < 3; c++) {
            float o0, o1;
            unpack2(oacc[r][c], o0, o1);
            float gg0 = g_g[off + 2*c], gg1 = g_g[off + 2*c + 1];
            *(ull*)&g_og[off + 2*c] = pack2(o0 * inv * gg0, o1 * inv * gg1);
        }
    }
}

extern "C" void kernel_launch(void* const* d_in, const int* in_sizes, int n_in,
                              void* d_out, int out_size)
{
    const float* s    = (const float*)d_in[0];
    const float* z    = (const float*)d_in[1];
    const float* mask = (const float*)d_in[2];
    const float* kin  = (const float*)d_in[3];
    const float* Wq   = (const float*)d_in[4];
    const float* bq   = (const float*)d_in[5];
    const float* Wk   = (const float*)d_in[6];
    const float* Wv   = (const float*)d_in[7];
    const float* Wg   = (const float*)d_in[8];
    const float* lng  = (const float*)d_in[9];
    const float* lnb  = (const float*)d_in[10];
    const float* Wz   = (const float*)d_in[11];
    const float* Wo   = (const float*)d_in[12];
    float* out = (float*)d_out;

    const int attn_smem = (48*IT + 48*JT + JT*48 + IT*PSS + IT + IT) * 4;
    cudaFuncSetAttribute(attn_kernel,
                         cudaFuncAttributeMaxDynamicSharedMemorySize, attn_smem);

    qkvg_kernel<<<dim3(CS/128, BB*NN/128, 4), 256>>>(s, kin, Wq, bq, Wk, Wv, Wg);
    biasproj_kernel<<<BB*NN*NN/256, 256>>>(z, lng, lnb, Wz);
    attn_kernel<<<dim3(NN/IT, BB*HH), 256, attn_smem>>>(mask);
    outproj_kernel<<<dim3(CS/128, BB*NN/128), 256>>>(Wo, out);
}